// round 1
// baseline (speedup 1.0000x reference)
#include <cuda_runtime.h>
#include <cstddef>

#define BN   16
#define HH   64
#define WW   64
#define CIN  128
#define CO   256
#define NPOS (HH*WW)

#define INS_F (3*66*128)      // input smem floats: 3 rows x (64+2 pad) x 128ch
#define WS_F  (32*256)        // weight chunk smem floats
#define SMEM_BYTES ((INS_F + WS_F)*4)

// Scratch (static __device__ arrays: the sanctioned alloc-free scratch)
__device__ float g_x [(size_t)BN*NPOS*CO]; // relu(conv) output, 67MB
__device__ float g_p0[BN*64*CO];           // per-(b,h) partial column sums (iter-1 s)
__device__ float g_p2[BN*64*CO];           // per-warp partials, pass 2
__device__ float g_p3[BN*64*CO];           // per-warp partials, pass 3
__device__ float g_v1[BN*CO];
__device__ float g_w [BN*CO];              // v1 + v2
__device__ float g_v3[BN*CO];

// ---------------------------------------------------------------------------
// Conv 3x3 SAME (implicit GEMM, fp32) + relu + bias, epilogue accumulates
// column sums (per (b,h) row) for routing iteration 1.
// Block = one (b,h) row: M=64 spatial, N=256 channels. 256 threads,
// thread fragment 4(m) x 16(n), n spread as co = j*64 + tx*4 (+0..3).
// ---------------------------------------------------------------------------
__global__ void __launch_bounds__(256, 1)
conv_kernel(const float* __restrict__ in, const float* __restrict__ wk,
            const float* __restrict__ bias)
{
    extern __shared__ float sm[];
    float* in_s = sm;             // [3][66][128], pad cols at wp=0,65
    float* w_s  = sm + INS_F;     // [32][256]
    const int h   = blockIdx.x;
    const int b   = blockIdx.y;
    const int tid = threadIdx.x;
    const int tx  = tid & 15;
    const int ty  = tid >> 4;

    // zero the pad columns
    if (tid < 192) {
        int r    = tid / 64;
        int side = (tid >> 5) & 1;
        int c4   = tid & 31;
        int wp   = side ? 65 : 0;
        ((float4*)in_s)[(r*66 + wp)*32 + c4] = make_float4(0.f, 0.f, 0.f, 0.f);
    }
    // load rows h-1..h+1 (zero outside image)
    for (int i = tid; i < 3*64*32; i += 256) {
        int r   = i >> 11;
        int rem = i & 2047;
        int w   = rem >> 5;
        int c4  = rem & 31;
        int hr  = h - 1 + r;
        float4 v = make_float4(0.f, 0.f, 0.f, 0.f);
        if (hr >= 0 && hr < HH)
            v = ((const float4*)in)[((size_t)(b*HH + hr)*WW + w)*32 + c4];
        ((float4*)in_s)[(r*66 + w + 1)*32 + c4] = v;
    }
    __syncthreads();

    float4 acc[4][4];
    #pragma unroll
    for (int i = 0; i < 4; i++)
        #pragma unroll
        for (int j = 0; j < 4; j++) acc[i][j] = make_float4(0.f, 0.f, 0.f, 0.f);

    for (int t = 0; t < 9; t++) {
        const int dh = t / 3, dw = t - dh*3;
        const float* ap_base = in_s + (dh*66 + ty*4 + dw)*128;
        for (int ci0 = 0; ci0 < 128; ci0 += 32) {
            __syncthreads();
            // weight chunk [(t,ci0..ci0+31) x 256] is contiguous in HWIO
            const float4* wsrc = ((const float4*)wk) + (size_t)(t*128 + ci0)*64;
            for (int i = tid; i < 2048; i += 256)
                ((float4*)w_s)[i] = wsrc[i];
            __syncthreads();

            const float* ap = ap_base + ci0;
            #pragma unroll 2
            for (int kk = 0; kk < 32; kk++) {
                float a0 = ap[kk];
                float a1 = ap[128 + kk];
                float a2 = ap[256 + kk];
                float a3 = ap[384 + kk];
                const float4* wr = ((const float4*)(w_s + kk*256)) + tx;
                #pragma unroll
                for (int j = 0; j < 4; j++) {
                    float4 wv = wr[j*16];
                    acc[0][j].x += a0*wv.x; acc[0][j].y += a0*wv.y; acc[0][j].z += a0*wv.z; acc[0][j].w += a0*wv.w;
                    acc[1][j].x += a1*wv.x; acc[1][j].y += a1*wv.y; acc[1][j].z += a1*wv.z; acc[1][j].w += a1*wv.w;
                    acc[2][j].x += a2*wv.x; acc[2][j].y += a2*wv.y; acc[2][j].z += a2*wv.z; acc[2][j].w += a2*wv.w;
                    acc[3][j].x += a3*wv.x; acc[3][j].y += a3*wv.y; acc[3][j].z += a3*wv.z; acc[3][j].w += a3*wv.w;
                }
            }
        }
    }

    __syncthreads();
    float4 bias4[4];
    #pragma unroll
    for (int j = 0; j < 4; j++) bias4[j] = ((const float4*)bias)[j*16 + tx];

    float4 psum[4];
    #pragma unroll
    for (int j = 0; j < 4; j++) psum[j] = make_float4(0.f, 0.f, 0.f, 0.f);

    float4* xout = ((float4*)g_x) + ((size_t)(b*HH + h)*WW)*64;
    #pragma unroll
    for (int i = 0; i < 4; i++) {
        int m = ty*4 + i;
        #pragma unroll
        for (int j = 0; j < 4; j++) {
            float4 o;
            o.x = fmaxf(acc[i][j].x + bias4[j].x, 0.f);
            o.y = fmaxf(acc[i][j].y + bias4[j].y, 0.f);
            o.z = fmaxf(acc[i][j].z + bias4[j].z, 0.f);
            o.w = fmaxf(acc[i][j].w + bias4[j].w, 0.f);
            xout[m*64 + j*16 + tx] = o;
            psum[j].x += o.x; psum[j].y += o.y; psum[j].z += o.z; psum[j].w += o.w;
        }
    }
    // deterministic reduce over ty (16 lanes of m-groups) via smem
    float4* sp = (float4*)w_s;   // reuse, 16x256 floats
    #pragma unroll
    for (int j = 0; j < 4; j++) sp[ty*64 + j*16 + tx] = psum[j];
    __syncthreads();
    float ssum = 0.f;
    const float* spf = w_s;
    #pragma unroll
    for (int r = 0; r < 16; r++) ssum += spf[r*256 + tid];
    g_p0[(b*64 + h)*256 + tid] = ssum;
}

// ---------------------------------------------------------------------------
// Routing pass: for each spatial n, logits = x[n]·v per capsule, softmax over
// capsules, accumulate c*x into per-warp partials. Lane l owns channels
// 8l..8l+7 (= half of capsule l/2). Deterministic: per-warp partial outputs.
// ---------------------------------------------------------------------------
__global__ void __launch_bounds__(256)
pass_kernel(const float* __restrict__ vvec, float* __restrict__ part)
{
    const int b    = blockIdx.y;
    const int bx   = blockIdx.x;        // 0..7, 512 n each
    const int wid  = threadIdx.x >> 5;  // 0..7
    const int lane = threadIdx.x & 31;

    float4 rv0 = ((const float4*)vvec)[b*64 + lane*2];
    float4 rv1 = ((const float4*)vvec)[b*64 + lane*2 + 1];
    float4 a0 = make_float4(0.f,0.f,0.f,0.f), a1 = make_float4(0.f,0.f,0.f,0.f);

    const float4* xb = ((const float4*)g_x) + (size_t)b*NPOS*64;
    int n = bx*512 + wid;
    #pragma unroll 4
    for (int it = 0; it < 64; it++, n += 8) {
        const float4* px = xb + (size_t)n*64 + lane*2;
        float4 xa = px[0];
        float4 xc = px[1];
        float dot = xa.x*rv0.x + xa.y*rv0.y + xa.z*rv0.z + xa.w*rv0.w
                  + xc.x*rv1.x + xc.y*rv1.y + xc.z*rv1.z + xc.w*rv1.w;
        dot += __shfl_xor_sync(0xffffffffu, dot, 1);   // full capsule dot (dup x2)
        float mx = dot;
        mx = fmaxf(mx, __shfl_xor_sync(0xffffffffu, mx, 2));
        mx = fmaxf(mx, __shfl_xor_sync(0xffffffffu, mx, 4));
        mx = fmaxf(mx, __shfl_xor_sync(0xffffffffu, mx, 8));
        mx = fmaxf(mx, __shfl_xor_sync(0xffffffffu, mx, 16));
        float e = __expf(dot - mx);
        float s = e;
        s += __shfl_xor_sync(0xffffffffu, s, 2);
        s += __shfl_xor_sync(0xffffffffu, s, 4);
        s += __shfl_xor_sync(0xffffffffu, s, 8);
        s += __shfl_xor_sync(0xffffffffu, s, 16);      // sum over 16 capsules
        float c = e / s;
        a0.x += c*xa.x; a0.y += c*xa.y; a0.z += c*xa.z; a0.w += c*xa.w;
        a1.x += c*xc.x; a1.y += c*xc.y; a1.z += c*xc.z; a1.w += c*xc.w;
    }
    float4* pp = (float4*)(part + ((size_t)(b*64 + bx*8 + wid))*256) + lane*2;
    pp[0] = a0;
    pp[1] = a1;
}

// ---------------------------------------------------------------------------
// Reduce 64 partials per (b,co), l2-normalize per capsule, optional +addv.
// Thread = one (b, capsule). One block of 256.
// ---------------------------------------------------------------------------
__global__ void vnorm_kernel(const float* __restrict__ part, float scale,
                             const float* __restrict__ addv, float* __restrict__ out)
{
    const int tid = threadIdx.x;
    const int b = tid >> 4, c = tid & 15;
    float s[16];
    #pragma unroll
    for (int d = 0; d < 16; d++) s[d] = 0.f;
    const float* p = part + (size_t)b*64*256 + c*16;
    for (int e = 0; e < 64; e++) {
        const float4* q = (const float4*)(p + e*256);
        float4 q0=q[0], q1=q[1], q2=q[2], q3=q[3];
        s[0]+=q0.x;  s[1]+=q0.y;  s[2]+=q0.z;  s[3]+=q0.w;
        s[4]+=q1.x;  s[5]+=q1.y;  s[6]+=q1.z;  s[7]+=q1.w;
        s[8]+=q2.x;  s[9]+=q2.y;  s[10]+=q2.z; s[11]+=q2.w;
        s[12]+=q3.x; s[13]+=q3.y; s[14]+=q3.z; s[15]+=q3.w;
    }
    float ss = 0.f;
    #pragma unroll
    for (int d = 0; d < 16; d++) { s[d] *= scale; ss += s[d]*s[d]; }
    float r = rsqrtf(fmaxf(ss, 1e-12f));
    float* o = out + b*256 + c*16;
    if (addv) {
        const float* av = addv + b*256 + c*16;
        #pragma unroll
        for (int d = 0; d < 16; d++) o[d] = s[d]*r + av[d];
    } else {
        #pragma unroll
        for (int d = 0; d < 16; d++) o[d] = s[d]*r;
    }
}

// Broadcast v3 over all spatial positions: out[b,h,w,:] = v3[b,:]
__global__ void __launch_bounds__(256)
bcast_kernel(float4* __restrict__ out, int total4)
{
    const float4* v = (const float4*)g_v3;
    for (int i = blockIdx.x*blockDim.x + threadIdx.x; i < total4;
         i += gridDim.x*blockDim.x)
        out[i] = v[((i >> 18) << 6) + (i & 63)];   // 2^18 float4 per batch, 64 f4 per v
}

extern "C" void kernel_launch(void* const* d_in, const int* in_sizes, int n_in,
                              void* d_out, int out_size)
{
    const float* in   = (const float*)d_in[0];
    const float* wk   = (const float*)d_in[1];
    const float* bias = (const float*)d_in[2];

    void *p0, *p2, *p3, *v1, *w, *v3;
    cudaGetSymbolAddress(&p0, g_p0);
    cudaGetSymbolAddress(&p2, g_p2);
    cudaGetSymbolAddress(&p3, g_p3);
    cudaGetSymbolAddress(&v1, g_v1);
    cudaGetSymbolAddress(&w,  g_w);
    cudaGetSymbolAddress(&v3, g_v3);

    cudaFuncSetAttribute(conv_kernel,
                         cudaFuncAttributeMaxDynamicSharedMemorySize, SMEM_BYTES);

    // conv + relu + iter-1 column sums
    conv_kernel<<<dim3(HH, BN), 256, SMEM_BYTES>>>(in, wk, bias);
    // v1 = normalize(sum_n x / 16)
    vnorm_kernel<<<1, 256>>>((const float*)p0, 1.f/16.f, nullptr, (float*)v1);
    // iter 2: s2 = sum_n softmax(x·v1) * x
    pass_kernel<<<dim3(8, BN), 256>>>((const float*)v1, (float*)p2);
    // w = v1 + normalize(s2)   (since b2 = x·(v1+v2))
    vnorm_kernel<<<1, 256>>>((const float*)p2, 1.f, (const float*)v1, (float*)w);
    // iter 3: s3 = sum_n softmax(x·w) * x
    pass_kernel<<<dim3(8, BN), 256>>>((const float*)w, (float*)p3);
    // v3 = normalize(s3)
    vnorm_kernel<<<1, 256>>>((const float*)p3, 1.f, nullptr, (float*)v3);
    // broadcast
    bcast_kernel<<<4096, 256>>>((float4*)d_out, out_size >> 2);
}

// round 3
// speedup vs baseline: 2.5398x; 2.5398x over previous
#include <cuda_runtime.h>
#include <cuda_bf16.h>
#include <cstdint>
#include <cstddef>

#define BN   16
#define HH   64
#define WW   64
#define CIN  128
#define CO   256
#define NPOS (HH*WW)
#define KTOT 1152

// ---------------- scratch (static device arrays) ----------------
__device__ __nv_bfloat16 g_ahi[(size_t)BN*HH*WW*CIN];
__device__ __nv_bfloat16 g_alo[(size_t)BN*HH*WW*CIN];
__device__ __nv_bfloat16 g_wThi[CO*KTOT];            // transposed weights [co][k]
__device__ __nv_bfloat16 g_wTlo[CO*KTOT];
__device__ __nv_bfloat16 g_x[(size_t)BN*NPOS*CO];    // relu(conv), bf16, 33.5MB
__device__ float g_p0[BN*32*CO];     // per (b, mtile) column sums (iter-1 s)
__device__ float g_p2[BN*64*CO];
__device__ float g_p3[BN*64*CO];
__device__ float g_v1[BN*CO];
__device__ float g_w [BN*CO];
__device__ float g_v3[BN*CO];

// ---------------- helpers ----------------
__device__ __forceinline__ uint32_t smem_u32(const void* p) {
    uint32_t a;
    asm("{ .reg .u64 t; cvta.to.shared.u64 t, %1; cvt.u32.u64 %0, t; }" : "=r"(a) : "l"(p));
    return a;
}
#define SW128(o) ((o) ^ (((o) >> 3) & 0x70))

__device__ __forceinline__ void cp16(uint32_t dst, const void* src, int srcsz) {
    asm volatile("cp.async.cg.shared.global [%0], [%1], 16, %2;"
                 :: "r"(dst), "l"(src), "r"(srcsz) : "memory");
}
#define CP_COMMIT() asm volatile("cp.async.commit_group;" ::: "memory")
#define CP_WAIT(n)  asm volatile("cp.async.wait_group %0;" :: "n"(n) : "memory")

__device__ __forceinline__ void ldm4(uint32_t* r, uint32_t a) {
    asm volatile("ldmatrix.sync.aligned.m8n8.x4.shared.b16 {%0,%1,%2,%3}, [%4];"
                 : "=r"(r[0]), "=r"(r[1]), "=r"(r[2]), "=r"(r[3]) : "r"(a));
}

__device__ __forceinline__ void mma16816(float* c, const uint32_t* a,
                                         uint32_t b0, uint32_t b1) {
    asm volatile(
        "mma.sync.aligned.m16n8k16.row.col.f32.bf16.bf16.f32 "
        "{%0,%1,%2,%3}, {%4,%5,%6,%7}, {%8,%9}, {%0,%1,%2,%3};"
        : "+f"(c[0]), "+f"(c[1]), "+f"(c[2]), "+f"(c[3])
        : "r"(a[0]), "r"(a[1]), "r"(a[2]), "r"(a[3]), "r"(b0), "r"(b1));
}

// ---------------- prep kernels ----------------
__global__ void __launch_bounds__(256)
split_in_kernel(const float4* __restrict__ in, int n4)
{
    __nv_bfloat162* hi = (__nv_bfloat162*)g_ahi;
    __nv_bfloat162* lo = (__nv_bfloat162*)g_alo;
    for (int i = blockIdx.x*blockDim.x + threadIdx.x; i < n4; i += gridDim.x*blockDim.x) {
        float4 v = in[i];
        __nv_bfloat162 h0 = __floats2bfloat162_rn(v.x, v.y);
        __nv_bfloat162 h1 = __floats2bfloat162_rn(v.z, v.w);
        __nv_bfloat162 l0 = __floats2bfloat162_rn(v.x - __bfloat162float(h0.x),
                                                  v.y - __bfloat162float(h0.y));
        __nv_bfloat162 l1 = __floats2bfloat162_rn(v.z - __bfloat162float(h1.x),
                                                  v.w - __bfloat162float(h1.y));
        hi[2*i] = h0; hi[2*i+1] = h1;
        lo[2*i] = l0; lo[2*i+1] = l1;
    }
}

__global__ void __launch_bounds__(256)
split_w_kernel(const float* __restrict__ wk)
{
    int k  = blockIdx.x;          // 0..1151 = tap*128 + ci
    int co = threadIdx.x;         // 0..255
    float v = wk[k*256 + co];
    __nv_bfloat16 h = __float2bfloat16(v);
    g_wThi[co*KTOT + k] = h;
    g_wTlo[co*KTOT + k] = __float2bfloat16(v - __bfloat162float(h));
}

// ---------------- tensor-core (HMMA) conv ----------------
// CTA: 128m (2 image rows) x 256n, 512 threads, warp grid 4m x 4n,
// warp tile 32m x 64n. K = 18 chunks of 64 (9 taps x 2 ci-halves),
// double-buffered smem, cp.async zfill handles SAME padding.
#define A_HI_OFF  0
#define A_LO_OFF  16384
#define B_HI_OFF  32768
#define B_LO_OFF  65536
#define BUF_BYTES 98304
#define CS_OFF    (2*BUF_BYTES)
#define BIAS_OFF  (CS_OFF + 4096)
#define SMEM_CONV (BIAS_OFF + 1024)

__global__ void __launch_bounds__(512, 1)
conv_mma_kernel(const float* __restrict__ bias)
{
    extern __shared__ char sm[];
    const uint32_t smb = smem_u32(sm);
    const int tid = threadIdx.x;
    const int tileIdx = blockIdx.x;   // 0..31 -> rows h0, h0+1
    const int b = blockIdx.y;
    const int h0 = tileIdx * 2;

    float* sbias = (float*)(sm + BIAS_OFF);
    if (tid < 256) sbias[tid] = bias[tid];

    // loader mapping
    const int am  = tid >> 2;     // A row m 0..127
    const int aq  = tid & 3;      // 2x16B chunks along k
    const int amh = am >> 6, amw = am & 63;
    const int bnr = tid >> 1;     // B row n 0..255
    const int bq  = tid & 1;      // 64B half of the 128B row

    // warp compute mapping
    const int wid = tid >> 5, lane = tid & 31;
    const int wm = (wid & 3) * 32;
    const int wn = (wid >> 2) * 64;
    const int lmat = lane >> 3, lrow = lane & 7;
    const int fr_row = (lmat & 1) * 8 + lrow;    // row within 16-row fragment
    const int fr_kb  = (lmat >> 1) * 16;         // 16B k-offset within 32B kstep

    float acc[2][8][4];
    #pragma unroll
    for (int mt = 0; mt < 2; mt++)
        #pragma unroll
        for (int nt = 0; nt < 8; nt++)
            #pragma unroll
            for (int j = 0; j < 4; j++) acc[mt][nt][j] = 0.f;

    auto issue_chunk = [&](int c) {
        const int tp = c >> 1, hf = c & 1;
        const int dh = tp / 3, dw = tp % 3;
        const uint32_t base = smb + (c & 1) * BUF_BYTES;
        // A tiles (hi/lo): [128m][64k] bf16, SW128
        {
            const int hsrc = h0 + amh + dh - 1;
            const int wsrc = amw + dw - 1;
            const bool ok = ((unsigned)hsrc < HH) && ((unsigned)wsrc < WW);
            const int hc = ok ? hsrc : 0, wc = ok ? wsrc : 0;
            const size_t e = (((size_t)(b*HH + hc)*WW + wc)*CIN) + hf*64 + aq*16;
            const int p = ok ? 16 : 0;
            const int o0 = am*128 + aq*32;
            cp16(base + A_HI_OFF + SW128(o0),      g_ahi + e,     p);
            cp16(base + A_HI_OFF + SW128(o0 + 16), g_ahi + e + 8, p);
            cp16(base + A_LO_OFF + SW128(o0),      g_alo + e,     p);
            cp16(base + A_LO_OFF + SW128(o0 + 16), g_alo + e + 8, p);
        }
        // B tiles (hi/lo): [256n][64k] bf16, SW128
        {
            const int kb = tp*128 + hf*64;
            const size_t e = (size_t)bnr*KTOT + kb + bq*32;
            const int o0 = bnr*128 + bq*64;
            #pragma unroll
            for (int j = 0; j < 4; j++) {
                cp16(base + B_HI_OFF + SW128(o0 + j*16), g_wThi + e + j*8, 16);
                cp16(base + B_LO_OFF + SW128(o0 + j*16), g_wTlo + e + j*8, 16);
            }
        }
        CP_COMMIT();
    };

    issue_chunk(0);
    for (int c = 0; c < 18; c++) {
        if (c < 17) { issue_chunk(c + 1); CP_WAIT(1); }
        else        { CP_WAIT(0); }
        __syncthreads();

        const uint32_t base = smb + (c & 1) * BUF_BYTES;
        #pragma unroll
        for (int ks = 0; ks < 4; ks++) {
            uint32_t aH[2][4], aL[2][4];
            #pragma unroll
            for (int mt = 0; mt < 2; mt++) {
                const int off = (wm + mt*16 + fr_row)*128 + ks*32 + fr_kb;
                ldm4(aH[mt], base + A_HI_OFF + SW128(off));
                ldm4(aL[mt], base + A_LO_OFF + SW128(off));
            }
            #pragma unroll
            for (int ng = 0; ng < 4; ng++) {
                const int off = (wn + ng*16 + fr_row)*128 + ks*32 + fr_kb;
                uint32_t bh[4], bl[4];
                ldm4(bh, base + B_HI_OFF + SW128(off));
                ldm4(bl, base + B_LO_OFF + SW128(off));
                #pragma unroll
                for (int mt = 0; mt < 2; mt++) {
                    // n8 tile 0 of this 16n group: regs {0,2}; tile 1: {1,3}
                    mma16816(acc[mt][ng*2],     aH[mt], bh[0], bh[2]);
                    mma16816(acc[mt][ng*2],     aH[mt], bl[0], bl[2]);
                    mma16816(acc[mt][ng*2],     aL[mt], bh[0], bh[2]);
                    mma16816(acc[mt][ng*2 + 1], aH[mt], bh[1], bh[3]);
                    mma16816(acc[mt][ng*2 + 1], aH[mt], bl[1], bl[3]);
                    mma16816(acc[mt][ng*2 + 1], aL[mt], bh[1], bh[3]);
                }
            }
        }
        __syncthreads();
    }

    // ---- epilogue: bias + relu, bf16 store, column sums ----
    float* cs = (float*)(sm + CS_OFF);   // [4 m-warp groups][256]
    const int r  = lane >> 2;
    const int cp = (lane & 3) * 2;
    const int wmIdx = wid & 3;

    float csum[8][2];
    #pragma unroll
    for (int nt = 0; nt < 8; nt++) { csum[nt][0] = 0.f; csum[nt][1] = 0.f; }

    #pragma unroll
    for (int mt = 0; mt < 2; mt++) {
        #pragma unroll
        for (int half = 0; half < 2; half++) {
            const int m = wm + mt*16 + r + half*8;
            const int h = h0 + (m >> 6), w = m & 63;
            __nv_bfloat16* dst = g_x + ((size_t)((b*HH + h)*WW + w))*CO + wn;
            #pragma unroll
            for (int nt = 0; nt < 8; nt++) {
                float o0 = fmaxf(acc[mt][nt][half*2]     + sbias[wn + nt*8 + cp],     0.f);
                float o1 = fmaxf(acc[mt][nt][half*2 + 1] + sbias[wn + nt*8 + cp + 1], 0.f);
                *(__nv_bfloat162*)(dst + nt*8 + cp) = __floats2bfloat162_rn(o0, o1);
                csum[nt][0] += o0;
                csum[nt][1] += o1;
            }
        }
    }
    #pragma unroll
    for (int nt = 0; nt < 8; nt++) {
        #pragma unroll
        for (int j = 0; j < 2; j++) {
            float v = csum[nt][j];
            v += __shfl_xor_sync(0xffffffffu, v, 4);
            v += __shfl_xor_sync(0xffffffffu, v, 8);
            v += __shfl_xor_sync(0xffffffffu, v, 16);
            if (lane < 4) cs[wmIdx*256 + wn + nt*8 + cp + j] = v;
        }
    }
    __syncthreads();
    if (tid < 256) {
        float s = cs[tid] + cs[256 + tid] + cs[512 + tid] + cs[768 + tid];
        g_p0[((size_t)b*32 + tileIdx)*256 + tid] = s;
    }
}

// ---------------- routing pass over bf16 x ----------------
__global__ void __launch_bounds__(256)
pass_kernel(const float* __restrict__ vvec, float* __restrict__ part)
{
    const int b    = blockIdx.y;
    const int bx   = blockIdx.x;        // 0..7
    const int wid  = threadIdx.x >> 5;
    const int lane = threadIdx.x & 31;

    float rv[8];
    #pragma unroll
    for (int j = 0; j < 8; j++) rv[j] = vvec[b*256 + lane*8 + j];
    float acc[8];
    #pragma unroll
    for (int j = 0; j < 8; j++) acc[j] = 0.f;

    const __nv_bfloat16* xb = g_x + (size_t)b*NPOS*CO;
    int n = bx*512 + wid;
    #pragma unroll 2
    for (int it = 0; it < 64; it++, n += 8) {
        uint4 raw = ((const uint4*)(xb + (size_t)n*CO))[lane];
        const __nv_bfloat162* pr = (const __nv_bfloat162*)&raw;
        float x[8];
        #pragma unroll
        for (int q = 0; q < 4; q++) {
            float2 f = __bfloat1622float2(pr[q]);
            x[2*q] = f.x; x[2*q+1] = f.y;
        }
        float dot = 0.f;
        #pragma unroll
        for (int j = 0; j < 8; j++) dot += x[j]*rv[j];
        dot += __shfl_xor_sync(0xffffffffu, dot, 1);   // full capsule dot
        float mx = dot;
        mx = fmaxf(mx, __shfl_xor_sync(0xffffffffu, mx, 2));
        mx = fmaxf(mx, __shfl_xor_sync(0xffffffffu, mx, 4));
        mx = fmaxf(mx, __shfl_xor_sync(0xffffffffu, mx, 8));
        mx = fmaxf(mx, __shfl_xor_sync(0xffffffffu, mx, 16));
        float e = __expf(dot - mx);
        float s = e;
        s += __shfl_xor_sync(0xffffffffu, s, 2);
        s += __shfl_xor_sync(0xffffffffu, s, 4);
        s += __shfl_xor_sync(0xffffffffu, s, 8);
        s += __shfl_xor_sync(0xffffffffu, s, 16);
        float cc = e / s;
        #pragma unroll
        for (int j = 0; j < 8; j++) acc[j] += cc * x[j];
    }
    float4* pp = (float4*)(part + ((size_t)(b*64 + bx*8 + wid))*256 + lane*8);
    pp[0] = make_float4(acc[0], acc[1], acc[2], acc[3]);
    pp[1] = make_float4(acc[4], acc[5], acc[6], acc[7]);
}

// ---------------- partial reduce + per-capsule l2 normalize ----------------
__global__ void __launch_bounds__(256)
vnorm_kernel(const float* __restrict__ part, int E,
             const float* __restrict__ addv, float* __restrict__ out)
{
    __shared__ float sv[256];
    const int b = blockIdx.x, tid = threadIdx.x;
    const float* p = part + (size_t)b*E*256 + tid;
    float s0=0.f,s1=0.f,s2=0.f,s3=0.f,s4=0.f,s5=0.f,s6=0.f,s7=0.f;
    for (int e = 0; e < E; e += 8) {
        s0 += p[(e+0)*256]; s1 += p[(e+1)*256];
        s2 += p[(e+2)*256]; s3 += p[(e+3)*256];
        s4 += p[(e+4)*256]; s5 += p[(e+5)*256];
        s6 += p[(e+6)*256]; s7 += p[(e+7)*256];
    }
    float s = ((s0+s1)+(s2+s3)) + ((s4+s5)+(s6+s7));
    sv[tid] = s;
    __syncthreads();
    const int cbase = (tid >> 4) << 4;
    float ss = 0.f;
    #pragma unroll
    for (int d = 0; d < 16; d++) { float v = sv[cbase + d]; ss += v*v; }
    float r = rsqrtf(fmaxf(ss, 1e-12f));
    float o = s * r;
    if (addv) o += addv[b*256 + tid];
    out[b*256 + tid] = o;
}

// ---------------- broadcast v3 ----------------
__global__ void __launch_bounds__(256)
bcast_kernel(float4* __restrict__ out, int total4)
{
    const float4* v = (const float4*)g_v3;
    for (int i = blockIdx.x*blockDim.x + threadIdx.x; i < total4;
         i += gridDim.x*blockDim.x)
        out[i] = v[((i >> 18) << 6) + (i & 63)];
}

extern "C" void kernel_launch(void* const* d_in, const int* in_sizes, int n_in,
                              void* d_out, int out_size)
{
    const float* in   = (const float*)d_in[0];
    const float* wk   = (const float*)d_in[1];
    const float* bias = (const float*)d_in[2];

    void *p0, *p2, *p3, *v1, *w, *v3;
    cudaGetSymbolAddress(&p0, g_p0);
    cudaGetSymbolAddress(&p2, g_p2);
    cudaGetSymbolAddress(&p3, g_p3);
    cudaGetSymbolAddress(&v1, g_v1);
    cudaGetSymbolAddress(&w,  g_w);
    cudaGetSymbolAddress(&v3, g_v3);

    cudaFuncSetAttribute(conv_mma_kernel,
                         cudaFuncAttributeMaxDynamicSharedMemorySize, SMEM_CONV);

    // prep: bf16 hi/lo splits of input and transposed weights
    split_in_kernel<<<2048, 256>>>((const float4*)in, (int)((size_t)BN*HH*WW*CIN/4));
    split_w_kernel<<<KTOT, 256>>>(wk);

    // conv on tensor cores (HMMA) + relu + iter-1 column sums
    conv_mma_kernel<<<dim3(32, BN), 512, SMEM_CONV>>>(bias);

    // routing
    vnorm_kernel<<<BN, 256>>>((const float*)p0, 32, nullptr, (float*)v1);
    pass_kernel<<<dim3(8, BN), 256>>>((const float*)v1, (float*)p2);
    vnorm_kernel<<<BN, 256>>>((const float*)p2, 64, (const float*)v1, (float*)w);
    pass_kernel<<<dim3(8, BN), 256>>>((const float*)w, (float*)p3);
    vnorm_kernel<<<BN, 256>>>((const float*)p3, 64, nullptr, (float*)v3);

    // broadcast v3 over spatial
    bcast_kernel<<<4096, 256>>>((float4*)d_out, out_size >> 2);
}

// round 4
// speedup vs baseline: 4.1488x; 1.6335x over previous
#include <cuda_runtime.h>
#include <cuda_fp16.h>
#include <cstdint>
#include <cstddef>

#define BN   16
#define HH   64
#define WW   64
#define CIN  128
#define CO   256
#define NPOS (HH*WW)

// ---------------- scratch ----------------
__device__ __half g_ahi[(size_t)BN*HH*WW*CIN];
__device__ __half g_alo[(size_t)BN*HH*WW*CIN];
__device__ uint4  g_wF[9*2*4*4*4*32];               // fragment-ordered fp16 weights
__device__ __half g_x[(size_t)BN*NPOS*CO];          // relu(conv), fp16, 33.5MB
__device__ float g_p0[BN*32*CO];
__device__ float g_p2[BN*64*CO];
__device__ float g_p3[BN*64*CO];
__device__ float g_v1[BN*CO];
__device__ float g_w [BN*CO];
__device__ float g_v3[BN*CO];

// ---------------- helpers ----------------
__device__ __forceinline__ uint32_t smem_u32(const void* p) {
    uint32_t a;
    asm("{ .reg .u64 t; cvta.to.shared.u64 t, %1; cvt.u32.u64 %0, t; }" : "=r"(a) : "l"(p));
    return a;
}
__device__ __forceinline__ void cp16(uint32_t dst, const void* src, int srcsz) {
    asm volatile("cp.async.cg.shared.global [%0], [%1], 16, %2;"
                 :: "r"(dst), "l"(src), "r"(srcsz) : "memory");
}
#define CP_COMMIT() asm volatile("cp.async.commit_group;" ::: "memory")
#define CP_WAIT(n)  asm volatile("cp.async.wait_group %0;" :: "n"(n) : "memory")

__device__ __forceinline__ void ldm4(uint32_t* r, uint32_t a) {
    asm volatile("ldmatrix.sync.aligned.m8n8.x4.shared.b16 {%0,%1,%2,%3}, [%4];"
                 : "=r"(r[0]), "=r"(r[1]), "=r"(r[2]), "=r"(r[3]) : "r"(a));
}
__device__ __forceinline__ void mma16816(float* c, const uint32_t* a,
                                         uint32_t b0, uint32_t b1) {
    asm volatile(
        "mma.sync.aligned.m16n8k16.row.col.f32.f16.f16.f32 "
        "{%0,%1,%2,%3}, {%4,%5,%6,%7}, {%8,%9}, {%0,%1,%2,%3};"
        : "+f"(c[0]), "+f"(c[1]), "+f"(c[2]), "+f"(c[3])
        : "r"(a[0]), "r"(a[1]), "r"(a[2]), "r"(a[3]), "r"(b0), "r"(b1));
}

// ---------------- prep kernels ----------------
__global__ void __launch_bounds__(256)
split_in_kernel(const float4* __restrict__ in, int n4)
{
    __half2* hi = (__half2*)g_ahi;
    __half2* lo = (__half2*)g_alo;
    for (int i = blockIdx.x*blockDim.x + threadIdx.x; i < n4; i += gridDim.x*blockDim.x) {
        float4 v = in[i];
        __half2 h0 = __floats2half2_rn(v.x, v.y);
        __half2 h1 = __floats2half2_rn(v.z, v.w);
        __half2 l0 = __floats2half2_rn(v.x - __half2float(__low2half(h0)),
                                       v.y - __half2float(__high2half(h0)));
        __half2 l1 = __floats2half2_rn(v.z - __half2float(__low2half(h1)),
                                       v.w - __half2float(__high2half(h1)));
        hi[2*i] = h0; hi[2*i+1] = h1;
        lo[2*i] = l0; lo[2*i+1] = l1;
    }
}

// Fragment-ordered weights: g_wF[((((tap*2+cih)*4+wnIdx)*4+ng)*4+ks)*32 + lane]
// = uint4 whose reg m (0..3), elem jj (0..1) is fp16 of
//   W[k = tap*128 + cih*64 + ks*16 + (m>>1)*8 + (lane&3)*2 + jj]
//    [n = wnIdx*64 + ng*16 + (m&1)*8 + (lane>>2)]
__global__ void __launch_bounds__(256)
split_w_kernel(const float* __restrict__ wk)
{
    int t = blockIdx.x*blockDim.x + threadIdx.x;   // 0..36863
    int lane = t & 31;
    int g = t >> 5;
    int ks = g & 3, ng = (g >> 2) & 3, wnIdx = (g >> 4) & 3;
    int cih = (g >> 6) & 1, tap = g >> 7;
    __half h[8];
    #pragma unroll
    for (int j = 0; j < 8; j++) {
        int m = j >> 1, jj = j & 1;
        int n = wnIdx*64 + ng*16 + (m & 1)*8 + (lane >> 2);
        int k = tap*128 + cih*64 + ks*16 + (m >> 1)*8 + (lane & 3)*2 + jj;
        h[j] = __float2half_rn(wk[k*256 + n]);
    }
    g_wF[t] = *(uint4*)h;
}

// ---------------- tensor-core conv, halo-reuse + B-via-LDG ----------------
// CTA: 128m (2 image rows) x 256n, 512 threads, warps 4m x 4n (32m x 64n each).
// A halo tile: 4 input rows x 66 w x 128 ci, fp16 hi+lo, loaded ONCE.
// 9 taps addressed by shifted ldmatrix rows; B fragments via LDG.128 from g_wF.
#define A_HI     0
#define A_LO     69632         // 4*68*256
#define CS_OFF   139264
#define BIAS_OFF 143360
#define SMEM_CONV 144384

__global__ void __launch_bounds__(512, 1)
conv_mma_kernel(const float* __restrict__ bias)
{
    extern __shared__ char sm[];
    const uint32_t smb = smem_u32(sm);
    const int tid = threadIdx.x;
    const int tileIdx = blockIdx.x;   // 0..31 -> rows h0, h0+1
    const int b = blockIdx.y;
    const int h0 = tileIdx * 2;

    float* sbias = (float*)(sm + BIAS_OFF);
    if (tid < 256) sbias[tid] = bias[tid];

    const int wid = tid >> 5, lane = tid & 31;
    const int wmIdx = wid & 3;          // m warp 0..3
    const int wnIdx = wid >> 2;         // n warp 0..3
    const int wm = wmIdx * 32;
    const int wn = wnIdx * 64;
    const int lmat = lane >> 3, lrow = lane & 7;
    const int fr_row = (lmat & 1)*8 + lrow;
    const int fr_kb  = (lmat >> 1)*16;

    float acc[2][8][4];
    #pragma unroll
    for (int mt = 0; mt < 2; mt++)
        #pragma unroll
        for (int nt = 0; nt < 8; nt++)
            #pragma unroll
            for (int j = 0; j < 4; j++) acc[mt][nt][j] = 0.f;

    // ---- A halo load: pixels (tr 0..3, tc 0..65), 32 x 16B parts each ----
    auto load_seg = [&](int i0, int i1) {
        for (int i = i0 + tid; i < i1; i += 512) {
            int pix  = i >> 5;
            int part = i & 31;
            int tr = pix / 66, tc = pix - tr*66;
            int h = h0 + tr - 1, w = tc - 1;
            bool ok = ((unsigned)h < HH) && ((unsigned)w < WW);
            int hc = ok ? h : 0, wc = ok ? w : 0;
            int slot = part & 15;
            uint32_t dst = smb + (part < 16 ? A_HI : A_LO)
                         + (tr*68 + tc)*256 + ((slot ^ (tc & 7)) << 4);
            const __half* base = (part < 16) ? g_ahi : g_alo;
            const __half* src = base + ((size_t)((b*HH + hc)*WW + wc))*CIN + slot*8;
            cp16(dst, src, ok ? 16 : 0);
        }
        CP_COMMIT();
    };
    load_seg(0, 4224);        // rows tr 0,1
    load_seg(4224, 8448);     // rows tr 2,3
    CP_WAIT(1);
    __syncthreads();

    const uint4* wf = g_wF + ((size_t)wnIdx << 9);   // + wnIdx*... folded below

    // precompute per-thread m decode for the two mt fragments
    int mw_[2], mr_[2];
    #pragma unroll
    for (int mt = 0; mt < 2; mt++) {
        int r_m = wm + mt*16 + fr_row;
        mr_[mt] = r_m >> 6;
        mw_[mt] = r_m & 63;
    }

    for (int tap = 0; tap < 9; tap++) {
        if (tap == 3) { CP_WAIT(0); __syncthreads(); }
        const int dh = tap / 3, dw = tap - dh*3;
        #pragma unroll
        for (int cih = 0; cih < 2; cih++) {
            const uint4* wfb = g_wF + ((((tap*2 + cih)*4 + wnIdx)*4)*4)*32 + lane;
            #pragma unroll
            for (int ks = 0; ks < 4; ks++) {
                uint32_t aH[2][4], aL[2][4];
                #pragma unroll
                for (int mt = 0; mt < 2; mt++) {
                    const int tr = mr_[mt] + dh;
                    const int tc = mw_[mt] + dw;
                    const int boff = cih*128 + ks*32 + fr_kb;
                    const uint32_t ad = smb + (tr*68 + tc)*256
                                      + (boff ^ ((tc & 7) << 4));
                    ldm4(aH[mt], ad + A_HI);
                    ldm4(aL[mt], ad + A_LO);
                }
                uint4 bv[4];
                #pragma unroll
                for (int ng = 0; ng < 4; ng++)
                    bv[ng] = wfb[(ng*4 + ks)*32];
                #pragma unroll
                for (int ng = 0; ng < 4; ng++) {
                    #pragma unroll
                    for (int mt = 0; mt < 2; mt++) {
                        mma16816(acc[mt][ng*2],     aH[mt], bv[ng].x, bv[ng].z);
                        mma16816(acc[mt][ng*2],     aL[mt], bv[ng].x, bv[ng].z);
                        mma16816(acc[mt][ng*2 + 1], aH[mt], bv[ng].y, bv[ng].w);
                        mma16816(acc[mt][ng*2 + 1], aL[mt], bv[ng].y, bv[ng].w);
                    }
                }
            }
        }
    }
    (void)wf;
    __syncthreads();

    // ---- epilogue: bias + relu, fp16 store, column sums ----
    float* cs = (float*)(sm + CS_OFF);   // [4 m-warps][256]
    const int r  = lane >> 2;
    const int cp = (lane & 3) * 2;

    float csum[8][2];
    #pragma unroll
    for (int nt = 0; nt < 8; nt++) { csum[nt][0] = 0.f; csum[nt][1] = 0.f; }

    #pragma unroll
    for (int mt = 0; mt < 2; mt++) {
        #pragma unroll
        for (int half = 0; half < 2; half++) {
            const int m = wm + mt*16 + r + half*8;
            const int h = h0 + (m >> 6), w = m & 63;
            __half* dst = g_x + ((size_t)((b*HH + h)*WW + w))*CO + wn;
            #pragma unroll
            for (int nt = 0; nt < 8; nt++) {
                float o0 = fmaxf(acc[mt][nt][half*2]     + sbias[wn + nt*8 + cp],     0.f);
                float o1 = fmaxf(acc[mt][nt][half*2 + 1] + sbias[wn + nt*8 + cp + 1], 0.f);
                *(__half2*)(dst + nt*8 + cp) = __floats2half2_rn(o0, o1);
                csum[nt][0] += o0;
                csum[nt][1] += o1;
            }
        }
    }
    #pragma unroll
    for (int nt = 0; nt < 8; nt++) {
        #pragma unroll
        for (int j = 0; j < 2; j++) {
            float v = csum[nt][j];
            v += __shfl_xor_sync(0xffffffffu, v, 4);
            v += __shfl_xor_sync(0xffffffffu, v, 8);
            v += __shfl_xor_sync(0xffffffffu, v, 16);
            if (lane < 4) cs[wmIdx*256 + wn + nt*8 + cp + j] = v;
        }
    }
    __syncthreads();
    if (tid < 256) {
        float s = cs[tid] + cs[256 + tid] + cs[512 + tid] + cs[768 + tid];
        g_p0[((size_t)b*32 + tileIdx)*256 + tid] = s;
    }
}

// ---------------- routing pass over fp16 x ----------------
__global__ void __launch_bounds__(256)
pass_kernel(const float* __restrict__ vvec, float* __restrict__ part)
{
    const int b    = blockIdx.y;
    const int bx   = blockIdx.x;        // 0..7
    const int wid  = threadIdx.x >> 5;
    const int lane = threadIdx.x & 31;

    float rv[8];
    #pragma unroll
    for (int j = 0; j < 8; j++) rv[j] = vvec[b*256 + lane*8 + j];
    float acc[8];
    #pragma unroll
    for (int j = 0; j < 8; j++) acc[j] = 0.f;

    const __half* xb = g_x + (size_t)b*NPOS*CO;
    int n = bx*512 + wid;
    #pragma unroll 2
    for (int it = 0; it < 64; it++, n += 8) {
        uint4 raw = ((const uint4*)(xb + (size_t)n*CO))[lane];
        const __half2* pr = (const __half2*)&raw;
        float x[8];
        #pragma unroll
        for (int q = 0; q < 4; q++) {
            float2 f = __half22float2(pr[q]);
            x[2*q] = f.x; x[2*q+1] = f.y;
        }
        float dot = 0.f;
        #pragma unroll
        for (int j = 0; j < 8; j++) dot += x[j]*rv[j];
        dot += __shfl_xor_sync(0xffffffffu, dot, 1);
        float mx = dot;
        mx = fmaxf(mx, __shfl_xor_sync(0xffffffffu, mx, 2));
        mx = fmaxf(mx, __shfl_xor_sync(0xffffffffu, mx, 4));
        mx = fmaxf(mx, __shfl_xor_sync(0xffffffffu, mx, 8));
        mx = fmaxf(mx, __shfl_xor_sync(0xffffffffu, mx, 16));
        float e = __expf(dot - mx);
        float s = e;
        s += __shfl_xor_sync(0xffffffffu, s, 2);
        s += __shfl_xor_sync(0xffffffffu, s, 4);
        s += __shfl_xor_sync(0xffffffffu, s, 8);
        s += __shfl_xor_sync(0xffffffffu, s, 16);
        float cc = e / s;
        #pragma unroll
        for (int j = 0; j < 8; j++) acc[j] += cc * x[j];
    }
    float4* pp = (float4*)(part + ((size_t)(b*64 + bx*8 + wid))*256 + lane*8);
    pp[0] = make_float4(acc[0], acc[1], acc[2], acc[3]);
    pp[1] = make_float4(acc[4], acc[5], acc[6], acc[7]);
}

// ---------------- partial reduce + per-capsule l2 normalize ----------------
__global__ void __launch_bounds__(256)
vnorm_kernel(const float* __restrict__ part, int E,
             const float* __restrict__ addv, float* __restrict__ out)
{
    __shared__ float sv[256];
    const int b = blockIdx.x, tid = threadIdx.x;
    const float* p = part + (size_t)b*E*256 + tid;
    float s0=0.f,s1=0.f,s2=0.f,s3=0.f,s4=0.f,s5=0.f,s6=0.f,s7=0.f;
    for (int e = 0; e < E; e += 8) {
        s0 += p[(e+0)*256]; s1 += p[(e+1)*256];
        s2 += p[(e+2)*256]; s3 += p[(e+3)*256];
        s4 += p[(e+4)*256]; s5 += p[(e+5)*256];
        s6 += p[(e+6)*256]; s7 += p[(e+7)*256];
    }
    float s = ((s0+s1)+(s2+s3)) + ((s4+s5)+(s6+s7));
    sv[tid] = s;
    __syncthreads();
    const int cbase = (tid >> 4) << 4;
    float ss = 0.f;
    #pragma unroll
    for (int d = 0; d < 16; d++) { float v = sv[cbase + d]; ss += v*v; }
    float r = rsqrtf(fmaxf(ss, 1e-12f));
    float o = s * r;
    if (addv) o += addv[b*256 + tid];
    out[b*256 + tid] = o;
}

// ---------------- broadcast v3 ----------------
__global__ void __launch_bounds__(256)
bcast_kernel(float4* __restrict__ out, int total4)
{
    const float4* v = (const float4*)g_v3;
    for (int i = blockIdx.x*blockDim.x + threadIdx.x; i < total4;
         i += gridDim.x*blockDim.x)
        out[i] = v[((i >> 18) << 6) + (i & 63)];
}

extern "C" void kernel_launch(void* const* d_in, const int* in_sizes, int n_in,
                              void* d_out, int out_size)
{
    const float* in   = (const float*)d_in[0];
    const float* wk   = (const float*)d_in[1];
    const float* bias = (const float*)d_in[2];

    void *p0, *p2, *p3, *v1, *w, *v3;
    cudaGetSymbolAddress(&p0, g_p0);
    cudaGetSymbolAddress(&p2, g_p2);
    cudaGetSymbolAddress(&p3, g_p3);
    cudaGetSymbolAddress(&v1, g_v1);
    cudaGetSymbolAddress(&w,  g_w);
    cudaGetSymbolAddress(&v3, g_v3);

    cudaFuncSetAttribute(conv_mma_kernel,
                         cudaFuncAttributeMaxDynamicSharedMemorySize, SMEM_CONV);

    split_in_kernel<<<2048, 256>>>((const float4*)in, (int)((size_t)BN*HH*WW*CIN/4));
    split_w_kernel<<<144, 256>>>(wk);

    conv_mma_kernel<<<dim3(32, BN), 512, SMEM_CONV>>>(bias);

    vnorm_kernel<<<BN, 256>>>((const float*)p0, 32, nullptr, (float*)v1);
    pass_kernel<<<dim3(8, BN), 256>>>((const float*)v1, (float*)p2);
    vnorm_kernel<<<BN, 256>>>((const float*)p2, 64, (const float*)v1, (float*)w);
    pass_kernel<<<dim3(8, BN), 256>>>((const float*)w, (float*)p3);
    vnorm_kernel<<<BN, 256>>>((const float*)p3, 64, nullptr, (float*)v3);

    bcast_kernel<<<4096, 256>>>((float4*)d_out, out_size >> 2);
}

// round 5
// speedup vs baseline: 7.0870x; 1.7082x over previous
#include <cuda_runtime.h>
#include <cuda_fp16.h>
#include <cstdint>
#include <cstddef>

#define BN   16
#define HH   64
#define WW   64
#define CIN  128
#define CO   256
#define NPOS (HH*WW)

// ---------------- scratch ----------------
__device__ __half g_ahi[(size_t)BN*HH*WW*CIN];      // fp16 input
__device__ uint4  g_wF[9*2*4*4*4*32];               // fragment-ordered fp16 weights
__device__ __half g_x[(size_t)BN*NPOS*CO];          // relu(conv), fp16, 33.5MB
__device__ float g_p0[BN*32*CO];
__device__ float g_p2[BN*128*CO];
__device__ float g_p3[BN*128*CO];
__device__ float g_v1[BN*CO];
__device__ float g_w [BN*CO];
__device__ float g_v3[BN*CO];

// ---------------- helpers ----------------
__device__ __forceinline__ uint32_t smem_u32(const void* p) {
    uint32_t a;
    asm("{ .reg .u64 t; cvta.to.shared.u64 t, %1; cvt.u32.u64 %0, t; }" : "=r"(a) : "l"(p));
    return a;
}
__device__ __forceinline__ void cp16(uint32_t dst, const void* src, int srcsz) {
    asm volatile("cp.async.cg.shared.global [%0], [%1], 16, %2;"
                 :: "r"(dst), "l"(src), "r"(srcsz) : "memory");
}
#define CP_COMMIT() asm volatile("cp.async.commit_group;" ::: "memory")
#define CP_WAIT(n)  asm volatile("cp.async.wait_group %0;" :: "n"(n) : "memory")

__device__ __forceinline__ void ldm4(uint32_t* r, uint32_t a) {
    asm volatile("ldmatrix.sync.aligned.m8n8.x4.shared.b16 {%0,%1,%2,%3}, [%4];"
                 : "=r"(r[0]), "=r"(r[1]), "=r"(r[2]), "=r"(r[3]) : "r"(a));
}
__device__ __forceinline__ void mma16816(float* c, const uint32_t* a,
                                         uint32_t b0, uint32_t b1) {
    asm volatile(
        "mma.sync.aligned.m16n8k16.row.col.f32.f16.f16.f32 "
        "{%0,%1,%2,%3}, {%4,%5,%6,%7}, {%8,%9}, {%0,%1,%2,%3};"
        : "+f"(c[0]), "+f"(c[1]), "+f"(c[2]), "+f"(c[3])
        : "r"(a[0]), "r"(a[1]), "r"(a[2]), "r"(a[3]), "r"(b0), "r"(b1));
}

// ---------------- prep kernels ----------------
__global__ void __launch_bounds__(256)
split_in_kernel(const float4* __restrict__ in, int n4)
{
    __half2* hi = (__half2*)g_ahi;
    for (int i = blockIdx.x*blockDim.x + threadIdx.x; i < n4; i += gridDim.x*blockDim.x) {
        float4 v = in[i];
        hi[2*i]   = __floats2half2_rn(v.x, v.y);
        hi[2*i+1] = __floats2half2_rn(v.z, v.w);
    }
}

// g_wF[((((tap*2+cih)*4+wnIdx)*4+ng)*4+ks)*32 + lane] packs 8 fp16:
//   reg m (0..3), elem jj (0..1):
//   W[k = tap*128+cih*64+ks*16+(m>>1)*8+(lane&3)*2+jj][n = wnIdx*64+ng*16+(m&1)*8+(lane>>2)]
__global__ void __launch_bounds__(256)
split_w_kernel(const float* __restrict__ wk)
{
    int t = blockIdx.x*blockDim.x + threadIdx.x;
    int lane = t & 31;
    int g = t >> 5;
    int ks = g & 3, ng = (g >> 2) & 3, wnIdx = (g >> 4) & 3;
    int cih = (g >> 6) & 1, tap = g >> 7;
    __half h[8];
    #pragma unroll
    for (int j = 0; j < 8; j++) {
        int m = j >> 1, jj = j & 1;
        int n = wnIdx*64 + ng*16 + (m & 1)*8 + (lane >> 2);
        int k = tap*128 + cih*64 + ks*16 + (m >> 1)*8 + (lane & 3)*2 + jj;
        h[j] = __float2half_rn(wk[k*256 + n]);
    }
    g_wF[t] = *(uint4*)h;
}

// ---------------- tensor-core conv ----------------
// CTA: 128m (2 image rows) x 256n, 256 threads, warps 2m x 4n (64m x 64n each).
// A halo tile (fp16): 4 input rows x 66 w x 128 ci, loaded once.
#define CS_OFF    69632            // A halo = 4*68*256 bytes
#define BIAS_OFF  (CS_OFF + 2048)
#define SMEM_CONV (BIAS_OFF + 1024)

__global__ void __launch_bounds__(256, 1)
conv_mma_kernel(const float* __restrict__ bias)
{
    extern __shared__ char sm[];
    const uint32_t smb = smem_u32(sm);
    const int tid = threadIdx.x;
    const int tileIdx = blockIdx.x;   // 0..31 -> rows h0, h0+1
    const int b = blockIdx.y;
    const int h0 = tileIdx * 2;

    float* sbias = (float*)(sm + BIAS_OFF);
    sbias[tid] = bias[tid];

    const int wid = tid >> 5, lane = tid & 31;
    const int wmIdx = wid & 1;          // m warp 0..1
    const int wnIdx = wid >> 1;         // n warp 0..3
    const int wm = wmIdx * 64;
    const int wn = wnIdx * 64;
    const int lmat = lane >> 3, lrow = lane & 7;
    const int fr_row = (lmat & 1)*8 + lrow;
    const int fr_kb  = (lmat >> 1)*16;

    float acc[4][8][4];
    #pragma unroll
    for (int mt = 0; mt < 4; mt++)
        #pragma unroll
        for (int nt = 0; nt < 8; nt++)
            #pragma unroll
            for (int j = 0; j < 4; j++) acc[mt][nt][j] = 0.f;

    // ---- A halo load: 264 pixels x 16 x 16B ----
    auto load_seg = [&](int i0, int i1) {
        for (int i = i0 + tid; i < i1; i += 256) {
            int pix  = i >> 4;
            int slot = i & 15;
            int tr = pix / 66, tc = pix - tr*66;
            int h = h0 + tr - 1, w = tc - 1;
            bool ok = ((unsigned)h < HH) && ((unsigned)w < WW);
            int hc = ok ? h : 0, wc = ok ? w : 0;
            uint32_t dst = smb + (tr*68 + tc)*256 + ((slot ^ (tc & 7)) << 4);
            const __half* src = g_ahi + ((size_t)((b*HH + hc)*WW + wc))*CIN + slot*8;
            cp16(dst, src, ok ? 16 : 0);
        }
        CP_COMMIT();
    };
    load_seg(0, 2112);        // input rows tr 0,1
    load_seg(2112, 4224);     // input rows tr 2,3
    CP_WAIT(1);
    __syncthreads();

    int mw_[4], mr_[4];
    #pragma unroll
    for (int mt = 0; mt < 4; mt++) {
        int r_m = wm + mt*16 + fr_row;
        mr_[mt] = r_m >> 6;
        mw_[mt] = r_m & 63;
    }

    for (int tap = 0; tap < 9; tap++) {
        if (tap == 3) { CP_WAIT(0); __syncthreads(); }
        const int dh = tap / 3, dw = tap - dh*3;
        #pragma unroll
        for (int cih = 0; cih < 2; cih++) {
            const uint4* wfb = g_wF + (((tap*2 + cih)*4 + wnIdx)*16)*32 + lane;
            #pragma unroll
            for (int ks = 0; ks < 4; ks++) {
                uint4 bv[4];
                #pragma unroll
                for (int ng = 0; ng < 4; ng++)
                    bv[ng] = wfb[(ng*4 + ks)*32];
                uint32_t aH[4][4];
                #pragma unroll
                for (int mt = 0; mt < 4; mt++) {
                    const int tr = mr_[mt] + dh;
                    const int tc = mw_[mt] + dw;
                    const uint32_t ad = smb + (tr*68 + tc)*256
                                      + ((cih*128 + ks*32 + fr_kb) ^ ((tc & 7) << 4));
                    ldm4(aH[mt], ad);
                }
                #pragma unroll
                for (int ng = 0; ng < 4; ng++) {
                    #pragma unroll
                    for (int mt = 0; mt < 4; mt++) {
                        mma16816(acc[mt][ng*2],     aH[mt], bv[ng].x, bv[ng].z);
                        mma16816(acc[mt][ng*2 + 1], aH[mt], bv[ng].y, bv[ng].w);
                    }
                }
            }
        }
    }
    __syncthreads();

    // ---- epilogue: bias + relu, fp16 store, column sums ----
    float* cs = (float*)(sm + CS_OFF);   // [2 m-warps][256]
    const int r  = lane >> 2;
    const int cp = (lane & 3) * 2;

    float csum[8][2];
    #pragma unroll
    for (int nt = 0; nt < 8; nt++) { csum[nt][0] = 0.f; csum[nt][1] = 0.f; }

    #pragma unroll
    for (int mt = 0; mt < 4; mt++) {
        #pragma unroll
        for (int half = 0; half < 2; half++) {
            const int m = wm + mt*16 + r + half*8;
            const int h = h0 + (m >> 6), w = m & 63;
            __half* dst = g_x + ((size_t)((b*HH + h)*WW + w))*CO + wn;
            #pragma unroll
            for (int nt = 0; nt < 8; nt++) {
                float o0 = fmaxf(acc[mt][nt][half*2]     + sbias[wn + nt*8 + cp],     0.f);
                float o1 = fmaxf(acc[mt][nt][half*2 + 1] + sbias[wn + nt*8 + cp + 1], 0.f);
                *(__half2*)(dst + nt*8 + cp) = __floats2half2_rn(o0, o1);
                csum[nt][0] += o0;
                csum[nt][1] += o1;
            }
        }
    }
    #pragma unroll
    for (int nt = 0; nt < 8; nt++) {
        #pragma unroll
        for (int j = 0; j < 2; j++) {
            float v = csum[nt][j];
            v += __shfl_xor_sync(0xffffffffu, v, 4);
            v += __shfl_xor_sync(0xffffffffu, v, 8);
            v += __shfl_xor_sync(0xffffffffu, v, 16);
            if (lane < 4) cs[wmIdx*256 + wn + nt*8 + cp + j] = v;
        }
    }
    __syncthreads();
    g_p0[((size_t)b*32 + tileIdx)*256 + tid] = cs[tid] + cs[256 + tid];
}

// ---------------- routing pass over fp16 x ----------------
__global__ void __launch_bounds__(256)
pass_kernel(const float* __restrict__ vvec, float* __restrict__ part)
{
    const int b    = blockIdx.y;
    const int bx   = blockIdx.x;        // 0..15, 256 n each
    const int wid  = threadIdx.x >> 5;
    const int lane = threadIdx.x & 31;

    float rv[8];
    #pragma unroll
    for (int j = 0; j < 8; j++) rv[j] = vvec[b*256 + lane*8 + j];
    float acc[8];
    #pragma unroll
    for (int j = 0; j < 8; j++) acc[j] = 0.f;

    const __half* xb = g_x + (size_t)b*NPOS*CO;
    int n = bx*256 + wid;
    #pragma unroll 2
    for (int it = 0; it < 32; it++, n += 8) {
        uint4 raw = ((const uint4*)(xb + (size_t)n*CO))[lane];
        const __half2* pr = (const __half2*)&raw;
        float x[8];
        #pragma unroll
        for (int q = 0; q < 4; q++) {
            float2 f = __half22float2(pr[q]);
            x[2*q] = f.x; x[2*q+1] = f.y;
        }
        float dot = 0.f;
        #pragma unroll
        for (int j = 0; j < 8; j++) dot += x[j]*rv[j];
        dot += __shfl_xor_sync(0xffffffffu, dot, 1);
        float mx = dot;
        mx = fmaxf(mx, __shfl_xor_sync(0xffffffffu, mx, 2));
        mx = fmaxf(mx, __shfl_xor_sync(0xffffffffu, mx, 4));
        mx = fmaxf(mx, __shfl_xor_sync(0xffffffffu, mx, 8));
        mx = fmaxf(mx, __shfl_xor_sync(0xffffffffu, mx, 16));
        float e = __expf(dot - mx);
        float s = e;
        s += __shfl_xor_sync(0xffffffffu, s, 2);
        s += __shfl_xor_sync(0xffffffffu, s, 4);
        s += __shfl_xor_sync(0xffffffffu, s, 8);
        s += __shfl_xor_sync(0xffffffffu, s, 16);
        float cc = e / s;
        #pragma unroll
        for (int j = 0; j < 8; j++) acc[j] += cc * x[j];
    }
    float4* pp = (float4*)(part + ((size_t)(b*128 + bx*8 + wid))*256 + lane*8);
    pp[0] = make_float4(acc[0], acc[1], acc[2], acc[3]);
    pp[1] = make_float4(acc[4], acc[5], acc[6], acc[7]);
}

// ---------------- partial reduce + per-capsule l2 normalize ----------------
__global__ void __launch_bounds__(1024)
vnorm_kernel(const float* __restrict__ part, int E,
             const float* __restrict__ addv, float* __restrict__ out)
{
    __shared__ float sv[1024];
    const int b = blockIdx.x, t = threadIdx.x;
    const int co = t & 255, q = t >> 8;
    const int eq = E >> 2;
    const float* p = part + ((size_t)b*E + q*eq)*256 + co;
    float s = 0.f;
    for (int e = 0; e < eq; e++) s += p[e*256];
    sv[t] = s;
    __syncthreads();
    if (t < 256) sv[t] = sv[t] + sv[256 + t] + sv[512 + t] + sv[768 + t];
    __syncthreads();
    if (t < 256) {
        const int cbase = (t >> 4) << 4;
        float ss = 0.f;
        #pragma unroll
        for (int d = 0; d < 16; d++) { float v = sv[cbase + d]; ss += v*v; }
        float r = rsqrtf(fmaxf(ss, 1e-12f));
        float o = sv[t] * r;
        if (addv) o += addv[b*256 + t];
        out[b*256 + t] = o;
    }
}

// ---------------- broadcast v3 ----------------
__global__ void __launch_bounds__(256)
bcast_kernel(float4* __restrict__ out, int total4)
{
    const float4* v = (const float4*)g_v3;
    for (int i = blockIdx.x*blockDim.x + threadIdx.x; i < total4;
         i += gridDim.x*blockDim.x)
        out[i] = v[((i >> 18) << 6) + (i & 63)];
}

extern "C" void kernel_launch(void* const* d_in, const int* in_sizes, int n_in,
                              void* d_out, int out_size)
{
    const float* in   = (const float*)d_in[0];
    const float* wk   = (const float*)d_in[1];
    const float* bias = (const float*)d_in[2];

    void *p0, *p2, *p3, *v1, *w, *v3;
    cudaGetSymbolAddress(&p0, g_p0);
    cudaGetSymbolAddress(&p2, g_p2);
    cudaGetSymbolAddress(&p3, g_p3);
    cudaGetSymbolAddress(&v1, g_v1);
    cudaGetSymbolAddress(&w,  g_w);
    cudaGetSymbolAddress(&v3, g_v3);

    cudaFuncSetAttribute(conv_mma_kernel,
                         cudaFuncAttributeMaxDynamicSharedMemorySize, SMEM_CONV);

    split_in_kernel<<<2048, 256>>>((const float4*)in, (int)((size_t)BN*HH*WW*CIN/4));
    split_w_kernel<<<144, 256>>>(wk);

    conv_mma_kernel<<<dim3(32, BN), 256, SMEM_CONV>>>(bias);

    vnorm_kernel<<<BN, 1024>>>((const float*)p0, 32, nullptr, (float*)v1);
    pass_kernel<<<dim3(16, BN), 256>>>((const float*)v1, (float*)p2);
    vnorm_kernel<<<BN, 1024>>>((const float*)p2, 128, (const float*)v1, (float*)w);
    pass_kernel<<<dim3(16, BN), 256>>>((const float*)w, (float*)p3);
    vnorm_kernel<<<BN, 1024>>>((const float*)p3, 128, nullptr, (float*)v3);

    bcast_kernel<<<4096, 256>>>((float4*)d_out, out_size >> 2);
}